// round 14
// baseline (speedup 1.0000x reference)
#include <cuda_runtime.h>
#include <cuda_bf16.h>
#include <cuda_fp16.h>
#include <math.h>
#include <stdint.h>

// DeformableSpatialAttention — fused conv-GEMM + deform (lean), fp16 mma.sync
//   K0 : weights->g_wBh, biases->g_bias, tap tables g_tapi/g_tapf
//   K1 : channel mean+max reduce -> g_att (planes) + g_att2 (float2 packed)
//   K2 : per 64-px tile: halo->SMEM, im2col(LDS), fp16 GEMM, conv->SMEM(half),
//        deform (64px x 4 ways) -> g_attmap.  80.6KB SMEM => 2 blocks/SM.
//   K3 : out = x * attmap (streaming)

#define Bn   8
#define Cn   256
#define Hn   128
#define Wn   128
#define HW   (Hn*Wn)
#define PIXT (Bn*HW)      // 131072
#define KK   49
#define NOFF 98
#define NCH  147
#define NP   160          // padded N (channels)
#define KS2  120          // A k-stride in halves (240B rows)
#define CVS  66           // conv staging px-stride (halves)

__device__ float  g_att[Bn*2*HW];                  // [b][c][pix] (halo src)
__device__ float2 g_att2[Bn*HW];                   // [b][pix] = (avg, max)
__device__ float  g_attmap[Bn*HW];
__device__ __align__(16) __half g_wBh[NP*KS2];     // padded fp16 weights [n][k]
__device__ float  g_bias[NP];
__device__ int    g_tapi[KS2];                     // im2col tap info
__device__ float4 g_tapf[KK];                      // (dy-3, dx-3, w0, w1)

// ================= K0: weight prep + tables =================
__global__ void dsa_prep_kernel(const float* __restrict__ ow, const float* __restrict__ ob,
                                const float* __restrict__ mw, const float* __restrict__ mb,
                                const float* __restrict__ dw){
    int gtid   = blockIdx.x*blockDim.x + threadIdx.x;
    int stride = gridDim.x * blockDim.x;
    for (int i = gtid; i < NP*KS2; i += stride){
        int n = i / KS2;
        int k = i - n*KS2;
        float v = 0.f;
        if (k < NOFF){
            if      (n < NOFF) v = ow[n*NOFF + k];
            else if (n < NCH)  v = mw[(n-NOFF)*NOFF + k];
        }
        g_wBh[i] = __float2half_rn(v);
        if (k == 0)
            g_bias[n] = (n < NOFF) ? ob[n] : (n < NCH) ? mb[n-NOFF] : 0.f;
    }
    if (gtid < KS2){
        int k = gtid;
        if (k < NOFF){
            int c = (k >= KK) ? 1 : 0;
            int r = k - c*KK;
            g_tapi[k] = (c << 16) | ((r/7) << 8) | (r%7);
        } else g_tapi[k] = -1;
    }
    if (gtid < KK){
        g_tapf[gtid] = make_float4((float)(gtid/7) - 3.f, (float)(gtid%7) - 3.f,
                                   dw[gtid], dw[KK + gtid]);
    }
}

// ================= K1: channel reduce (float4, unroll16) =================
__global__ void dsa_reduce_kernel(const float* __restrict__ x){
    int t  = blockIdx.x * 128 + threadIdx.x;     // 256 blocks x 128 thr
    int b  = t >> 12;
    int p4 = t & 4095;
    const float4* base = (const float4*)x + (size_t)b*(Cn*HW/4) + p4;
    float4 s = make_float4(0.f,0.f,0.f,0.f);
    float4 m = make_float4(-1e30f,-1e30f,-1e30f,-1e30f);
    #pragma unroll 16
    for (int c = 0; c < Cn; c++){
        float4 v = __ldcs(base + c*(HW/4));
        s.x += v.x; s.y += v.y; s.z += v.z; s.w += v.w;
        m.x = fmaxf(m.x, v.x); m.y = fmaxf(m.y, v.y);
        m.z = fmaxf(m.z, v.z); m.w = fmaxf(m.w, v.w);
    }
    const float r = 1.f/256.f;
    float4 sm4 = make_float4(s.x*r, s.y*r, s.z*r, s.w*r);
    ((float4*)g_att)[b*(2*HW/4) + p4]        = sm4;
    ((float4*)g_att)[b*(2*HW/4) + HW/4 + p4] = m;
    int pix = (b << 14) + (p4 << 2);
    g_att2[pix    ] = make_float2(sm4.x, m.x);
    g_att2[pix + 1] = make_float2(sm4.y, m.y);
    g_att2[pix + 2] = make_float2(sm4.z, m.z);
    g_att2[pix + 3] = make_float2(sm4.w, m.w);
}

// ================= K2: fused conv GEMM + deform =================
// SMEM (bytes)
#define SMB_HALO 0                 // 2*7*72 floats = 4032 -> pad 4096
#define SMB_A    4096              // 64*120 half = 15360 -> 19456
#define SMB_B    19456             // 160*120 half = 38400 -> 57856
#define SMB_CONV 57856             // 160*66 half = 21120 -> 78976
#define SMB_BIAS 78976             // 160*4 = 640 -> 79616
#define SMB_PART 79616             // 256*4 = 1024 -> 80640
#define SMB_TOTAL 80640

__global__ __launch_bounds__(256, 2)
void dsa_fused_kernel(){
    extern __shared__ char sm[];
    float*  halo  = (float*)(sm + SMB_HALO);
    __half* Ash   = (__half*)(sm + SMB_A);
    __half* Bsh   = (__half*)(sm + SMB_B);
    __half* convs = (__half*)(sm + SMB_CONV);
    float*  biass = (float*)(sm + SMB_BIAS);
    float*  parts = (float*)(sm + SMB_PART);

    const int tid  = threadIdx.x;
    const int wid  = tid >> 5;
    const int lane = tid & 31;
    const int g    = lane >> 2;
    const int tig  = lane & 3;

    const int blk = blockIdx.x;           // b(8) x y(128) x xh(2)
    const int xh  = blk & 1;
    const int y   = (blk >> 1) & 127;
    const int b   = blk >> 8;
    const int px0 = xh * 64;

    // ---- stage att halo [2][7][72] (coalesced rows, zero-padded) ----
    for (int i = tid; i < 2*7*72; i += 256){
        int c   = i / 504;
        int rem = i - c*504;
        int dy  = rem / 72;
        int xx  = rem - dy*72;
        int gy  = y + dy - 3;
        int gx  = px0 + xx - 3;
        float v = 0.f;
        if ((unsigned)gy < (unsigned)Hn && (unsigned)gx < (unsigned)Wn)
            v = __ldg(g_att + ((b*2 + c) << 14) + (gy << 7) + gx);
        halo[i] = v;
    }
    // ---- copy B weights into SMEM ----
    {
        const float4* src = (const float4*)g_wBh;
        float4* dst = (float4*)Bsh;
        #pragma unroll
        for (int i = tid; i < (NP*KS2*2)/16; i += 256) dst[i] = src[i];
    }
    if (tid < NP) biass[tid] = g_bias[tid];
    __syncthreads();

    // ---- im2col A (half) [64 px][120 k] from SMEM halo ----
    {
        const int px = tid & 63;
        #pragma unroll
        for (int it = 0; it < 30; it++){
            int k = (tid >> 6) + it*4;          // 0..119
            int info = __ldg(g_tapi + k);
            float v = 0.f;
            if (info >= 0){
                int c  = info >> 16;
                int dy = (info >> 8) & 255;
                int dx = info & 255;
                v = halo[c*504 + dy*72 + px + dx];
            }
            Ash[px*KS2 + k] = __float2half_rn(v);
        }
    }
    __syncthreads();

    // ---- warp GEMM: 8 warps = 4(M)x2(N); per pass 16(M)x40(N), K=112 ----
    const int mrow  = (wid & 3) * 16;
    const int nbase = (wid >> 2) * 80;

    #pragma unroll 1
    for (int pass = 0; pass < 2; pass++){
        const int ncolp = nbase + pass*40;
        float acc[5][4];
        #pragma unroll
        for (int ni = 0; ni < 5; ni++)
            #pragma unroll
            for (int j = 0; j < 4; j++) acc[ni][j] = 0.f;

        #pragma unroll
        for (int ks = 0; ks < 7; ks++){
            const int k0 = ks*16;
            const uint32_t a0 = *(const uint32_t*)(Ash + (mrow+g  )*KS2 + k0 + 2*tig    );
            const uint32_t a1 = *(const uint32_t*)(Ash + (mrow+8+g)*KS2 + k0 + 2*tig    );
            const uint32_t a2 = *(const uint32_t*)(Ash + (mrow+g  )*KS2 + k0 + 2*tig + 8);
            const uint32_t a3 = *(const uint32_t*)(Ash + (mrow+8+g)*KS2 + k0 + 2*tig + 8);
            #pragma unroll
            for (int ni = 0; ni < 5; ni++){
                const int n0 = ncolp + ni*8;
                const __half* bp = Bsh + (n0+g)*KS2 + k0 + 2*tig;
                uint32_t b0 = *(const uint32_t*)bp;
                uint32_t b1 = *(const uint32_t*)(bp + 8);
                asm volatile(
                    "mma.sync.aligned.m16n8k16.row.col.f32.f16.f16.f32 "
                    "{%0,%1,%2,%3}, {%4,%5,%6,%7}, {%8,%9}, {%0,%1,%2,%3};"
                    : "+f"(acc[ni][0]), "+f"(acc[ni][1]),
                      "+f"(acc[ni][2]), "+f"(acc[ni][3])
                    : "r"(a0), "r"(a1), "r"(a2), "r"(a3), "r"(b0), "r"(b1));
            }
        }

        // ---- epilogue: bias + mask sigmoid -> convs[ch][px] (half, SMEM) ----
        #pragma unroll
        for (int ni = 0; ni < 5; ni++){
            const int n0 = ncolp + ni*8 + 2*tig;
            #pragma unroll
            for (int j = 0; j < 4; j++){
                int ch = n0 + (j & 1);
                int px = mrow + g + ((j >> 1) << 3);
                if (ch < NCH){
                    float v = acc[ni][j] + biass[ch];
                    if (ch >= NOFF) v = 2.f/(1.f + __expf(-v));
                    convs[ch*CVS + px] = __float2half_rn(v);
                }
            }
        }
    }
    __syncthreads();

    // ---- deform: 64 px x 4 ways ----
    {
        const int way = tid >> 6;
        const int px  = tid & 63;
        const float yf = (float)y;
        const float xf = (float)(px0 + px);
        const float2* att = g_att2 + (b << 14);

        float part = 0.f;
        #pragma unroll
        for (int kk = way; kk < KK; kk += 4){
            float4 tc = __ldg(g_tapf + kk);          // (dy-3, dx-3, w0, w1)
            float oy = __half2float(convs[(2*kk  )*CVS + px]);
            float ox = __half2float(convs[(2*kk+1)*CVS + px]);
            float mk = __half2float(convs[(NOFF+kk)*CVS + px]);

            float py  = yf + tc.x + oy;
            float pxx = xf + tc.y + ox;

            float fy = floorf(py), fx = floorf(pxx);
            int y0 = (int)fy, x0 = (int)fx;
            int y1 = y0 + 1,  x1 = x0 + 1;
            float wy1 = py - fy,  wy0 = 1.f - wy1;
            float wx1 = pxx - fx, wx0 = 1.f - wx1;
            float s0 = 0.f, s1 = 0.f;
            bool yv0 = (unsigned)y0 < (unsigned)Hn, yv1 = (unsigned)y1 < (unsigned)Hn;
            bool xv0 = (unsigned)x0 < (unsigned)Wn, xv1 = (unsigned)x1 < (unsigned)Wn;
            if (yv0 && xv0){ float2 v = att[(y0<<7)+x0]; float w = wy0*wx0; s0 += w*v.x; s1 += w*v.y; }
            if (yv0 && xv1){ float2 v = att[(y0<<7)+x1]; float w = wy0*wx1; s0 += w*v.x; s1 += w*v.y; }
            if (yv1 && xv0){ float2 v = att[(y1<<7)+x0]; float w = wy1*wx0; s0 += w*v.x; s1 += w*v.y; }
            if (yv1 && xv1){ float2 v = att[(y1<<7)+x1]; float w = wy1*wx1; s0 += w*v.x; s1 += w*v.y; }

            part += (s0*tc.z + s1*tc.w) * mk;
        }
        parts[way*64 + px] = part;
    }
    __syncthreads();

    if (tid < 64){
        float d = parts[tid] + parts[64+tid] + parts[128+tid] + parts[192+tid];
        g_attmap[(b << 14) + (y << 7) + px0 + tid] = 1.f/(1.f + __expf(-d));
    }
}

// ================= K3: out = x * attmap (streaming) =================
__global__ void dsa_mul_kernel(const float* __restrict__ x,
                               float* __restrict__ out){
    int gid = blockIdx.x * 256 + threadIdx.x;       // float4 index
    float4 xv = __ldcs((const float4*)x + gid);
    int e   = gid << 2;
    int b   = e >> 22;
    int pix = e & 16383;
    float4 a = *(const float4*)(g_attmap + (b << 14) + pix);
    xv.x *= a.x; xv.y *= a.y; xv.z *= a.z; xv.w *= a.w;
    __stcs((float4*)out + gid, xv);
}

// ================= launch =================
extern "C" void kernel_launch(void* const* d_in, const int* in_sizes, int n_in,
                              void* d_out, int out_size){
    const float* x        = (const float*)d_in[0];
    const float* offset_w = (const float*)d_in[1];
    const float* offset_b = (const float*)d_in[2];
    const float* mod_w    = (const float*)d_in[3];
    const float* mod_b    = (const float*)d_in[4];
    const float* dconv_w  = (const float*)d_in[5];
    float* out = (float*)d_out;

    cudaFuncSetAttribute(dsa_fused_kernel,
                         cudaFuncAttributeMaxDynamicSharedMemorySize, SMB_TOTAL);

    dsa_prep_kernel<<<16, 512>>>(offset_w, offset_b, mod_w, mod_b, dconv_w);
    dsa_reduce_kernel<<<256, 128>>>(x);
    dsa_fused_kernel<<<Bn*Hn*2, 256, SMB_TOTAL>>>();
    dsa_mul_kernel<<<(Bn*Cn*HW/4)/256, 256>>>(x, out);
}

// round 15
// speedup vs baseline: 1.1195x; 1.1195x over previous
#include <cuda_runtime.h>
#include <cuda_bf16.h>
#include <cuda_fp16.h>
#include <math.h>
#include <stdint.h>

// DeformableSpatialAttention — fused conv+deform, fragment-ordered weights
//   K0 : weights -> g_wBf (per-lane MMA fragment order, L1-resident),
//        biases->g_bias, tap tables g_tapi/g_tapf
//   K1 : channel mean+max reduce -> g_att (planes) + g_att2 (float2 packed)
//   K2 : per 64-px tile: halo->SMEM, im2col(LDS), fp16 GEMM (B via coalesced
//        L1 __ldg), conv->SMEM(half), deform -> g_attmap. 42.2KB => 4 blk/SM.
//   K3 : out = x * attmap (streaming)

#define Bn   8
#define Cn   256
#define Hn   128
#define Wn   128
#define HW   (Hn*Wn)
#define KK   49
#define NOFF 98
#define NCH  147
#define NP   160          // padded N (channels)
#define KS2  120          // A k-stride in halves (240B rows)
#define CVS  66           // conv staging px-stride (halves)
#define NT   (NP/8)       // 20 n-tiles
#define KST  7            // k-steps

__device__ float  g_att[Bn*2*HW];                  // [b][c][pix] (halo src)
__device__ float2 g_att2[Bn*HW];                   // [b][pix] = (avg, max)
__device__ float  g_attmap[Bn*HW];
__device__ __align__(16) uint2 g_wBf[NT*KST*32];   // fragment-ordered weights
__device__ float  g_bias[NP];
__device__ int    g_tapi[KS2];                     // im2col tap info
__device__ float4 g_tapf[KK];                      // (dy-3, dx-3, w0, w1)

// ================= K0: weight prep + tables =================
__device__ __forceinline__ float wval(const float* ow, const float* mw, int n, int k){
    if (k >= NOFF) return 0.f;
    if (n < NOFF)  return ow[n*NOFF + k];
    if (n < NCH)   return mw[(n-NOFF)*NOFF + k];
    return 0.f;
}

__global__ void dsa_prep_kernel(const float* __restrict__ ow, const float* __restrict__ ob,
                                const float* __restrict__ mw, const float* __restrict__ mb,
                                const float* __restrict__ dw){
    int gtid   = blockIdx.x*blockDim.x + threadIdx.x;
    int stride = gridDim.x * blockDim.x;
    // fragment-ordered weights: [nt][ks][lane] -> uint2 {b0, b1}
    for (int i = gtid; i < NT*KST*32; i += stride){
        int nt   = i / (KST*32);
        int rem  = i - nt*(KST*32);
        int ks   = rem >> 5;
        int lane = rem & 31;
        int g    = lane >> 2;
        int tig  = lane & 3;
        int n    = nt*8 + g;
        int k0   = ks*16 + 2*tig;
        __half2 h0 = __floats2half2_rn(wval(ow,mw,n,k0  ), wval(ow,mw,n,k0+1));
        __half2 h1 = __floats2half2_rn(wval(ow,mw,n,k0+8), wval(ow,mw,n,k0+9));
        uint2 u;
        u.x = *(uint32_t*)&h0;
        u.y = *(uint32_t*)&h1;
        g_wBf[i] = u;
    }
    if (gtid < NP)
        g_bias[gtid] = (gtid < NOFF) ? ob[gtid] : (gtid < NCH) ? mb[gtid-NOFF] : 0.f;
    if (gtid < KS2){
        int k = gtid;
        if (k < NOFF){
            int c = (k >= KK) ? 1 : 0;
            int r = k - c*KK;
            g_tapi[k] = (c << 16) | ((r/7) << 8) | (r%7);
        } else g_tapi[k] = -1;
    }
    if (gtid < KK){
        g_tapf[gtid] = make_float4((float)(gtid/7) - 3.f, (float)(gtid%7) - 3.f,
                                   dw[gtid], dw[KK + gtid]);
    }
}

// ================= K1: channel reduce (float4, unroll16) =================
__global__ void dsa_reduce_kernel(const float* __restrict__ x){
    int t  = blockIdx.x * 128 + threadIdx.x;     // 256 blocks x 128 thr
    int b  = t >> 12;
    int p4 = t & 4095;
    const float4* base = (const float4*)x + (size_t)b*(Cn*HW/4) + p4;
    float4 s = make_float4(0.f,0.f,0.f,0.f);
    float4 m = make_float4(-1e30f,-1e30f,-1e30f,-1e30f);
    #pragma unroll 16
    for (int c = 0; c < Cn; c++){
        float4 v = __ldcs(base + c*(HW/4));
        s.x += v.x; s.y += v.y; s.z += v.z; s.w += v.w;
        m.x = fmaxf(m.x, v.x); m.y = fmaxf(m.y, v.y);
        m.z = fmaxf(m.z, v.z); m.w = fmaxf(m.w, v.w);
    }
    const float r = 1.f/256.f;
    float4 sm4 = make_float4(s.x*r, s.y*r, s.z*r, s.w*r);
    ((float4*)g_att)[b*(2*HW/4) + p4]        = sm4;
    ((float4*)g_att)[b*(2*HW/4) + HW/4 + p4] = m;
    int pix = (b << 14) + (p4 << 2);
    g_att2[pix    ] = make_float2(sm4.x, m.x);
    g_att2[pix + 1] = make_float2(sm4.y, m.y);
    g_att2[pix + 2] = make_float2(sm4.z, m.z);
    g_att2[pix + 3] = make_float2(sm4.w, m.w);
}

// ================= K2: fused conv GEMM + deform =================
// SMEM (bytes)
#define SMB_HALO 0                 // 2*7*72 floats = 4032 -> pad 4096
#define SMB_A    4096              // 64*120 half = 15360 -> 19456
#define SMB_CONV 19456             // 160*66 half = 21120 -> 40576
#define SMB_BIAS 40576             // 160*4 = 640 -> 41216
#define SMB_PART 41216             // 256*4 = 1024 -> 42240
#define SMB_TOTAL 42240

__global__ __launch_bounds__(256, 4)
void dsa_fused_kernel(){
    extern __shared__ char sm[];
    float*  halo  = (float*)(sm + SMB_HALO);
    __half* Ash   = (__half*)(sm + SMB_A);
    __half* convs = (__half*)(sm + SMB_CONV);
    float*  biass = (float*)(sm + SMB_BIAS);
    float*  parts = (float*)(sm + SMB_PART);

    const int tid  = threadIdx.x;
    const int wid  = tid >> 5;
    const int lane = tid & 31;
    const int g    = lane >> 2;
    const int tig  = lane & 3;

    const int blk = blockIdx.x;           // b(8) x y(128) x xh(2)
    const int xh  = blk & 1;
    const int y   = (blk >> 1) & 127;
    const int b   = blk >> 8;
    const int px0 = xh * 64;

    // ---- stage att halo [2][7][72] (coalesced rows, zero-padded) ----
    for (int i = tid; i < 2*7*72; i += 256){
        int c   = i / 504;
        int rem = i - c*504;
        int dy  = rem / 72;
        int xx  = rem - dy*72;
        int gy  = y + dy - 3;
        int gx  = px0 + xx - 3;
        float v = 0.f;
        if ((unsigned)gy < (unsigned)Hn && (unsigned)gx < (unsigned)Wn)
            v = __ldg(g_att + ((b*2 + c) << 14) + (gy << 7) + gx);
        halo[i] = v;
    }
    if (tid < NP) biass[tid] = g_bias[tid];
    __syncthreads();

    // ---- im2col A (half) [64 px][120 k] from SMEM halo ----
    {
        const int px = tid & 63;
        #pragma unroll
        for (int it = 0; it < 30; it++){
            int k = (tid >> 6) + it*4;          // 0..119
            int info = __ldg(g_tapi + k);
            float v = 0.f;
            if (info >= 0){
                int c  = info >> 16;
                int dy = (info >> 8) & 255;
                int dx = info & 255;
                v = halo[c*504 + dy*72 + px + dx];
            }
            Ash[px*KS2 + k] = __float2half_rn(v);
        }
    }
    __syncthreads();

    // ---- warp GEMM: 8 warps = 4(M)x2(N); per pass 16(M)x40(N), K=112 ----
    // B fragments via coalesced __ldg from g_wBf (L1-resident, 35KB)
    const int mrow  = (wid & 3) * 16;
    const int nbase = (wid >> 2) * 80;

    #pragma unroll 1
    for (int pass = 0; pass < 2; pass++){
        const int ncolp = nbase + pass*40;
        const int nt0   = ncolp >> 3;            // first n-tile of this pass
        float acc[5][4];
        #pragma unroll
        for (int ni = 0; ni < 5; ni++)
            #pragma unroll
            for (int j = 0; j < 4; j++) acc[ni][j] = 0.f;

        #pragma unroll
        for (int ks = 0; ks < KST; ks++){
            const int k0 = ks*16;
            const uint32_t a0 = *(const uint32_t*)(Ash + (mrow+g  )*KS2 + k0 + 2*tig    );
            const uint32_t a1 = *(const uint32_t*)(Ash + (mrow+8+g)*KS2 + k0 + 2*tig    );
            const uint32_t a2 = *(const uint32_t*)(Ash + (mrow+g  )*KS2 + k0 + 2*tig + 8);
            const uint32_t a3 = *(const uint32_t*)(Ash + (mrow+8+g)*KS2 + k0 + 2*tig + 8);
            #pragma unroll
            for (int ni = 0; ni < 5; ni++){
                uint2 bb = __ldg(g_wBf + ((nt0 + ni)*KST + ks)*32 + lane);
                asm volatile(
                    "mma.sync.aligned.m16n8k16.row.col.f32.f16.f16.f32 "
                    "{%0,%1,%2,%3}, {%4,%5,%6,%7}, {%8,%9}, {%0,%1,%2,%3};"
                    : "+f"(acc[ni][0]), "+f"(acc[ni][1]),
                      "+f"(acc[ni][2]), "+f"(acc[ni][3])
                    : "r"(a0), "r"(a1), "r"(a2), "r"(a3), "r"(bb.x), "r"(bb.y));
            }
        }

        // ---- epilogue: bias + mask sigmoid -> convs[ch][px] (half, SMEM) ----
        #pragma unroll
        for (int ni = 0; ni < 5; ni++){
            const int n0 = ncolp + ni*8 + 2*tig;
            #pragma unroll
            for (int j = 0; j < 4; j++){
                int ch = n0 + (j & 1);
                int px = mrow + g + ((j >> 1) << 3);
                if (ch < NCH){
                    float v = acc[ni][j] + biass[ch];
                    if (ch >= NOFF) v = 2.f/(1.f + __expf(-v));
                    convs[ch*CVS + px] = __float2half_rn(v);
                }
            }
        }
    }
    __syncthreads();

    // ---- deform: 64 px x 4 ways ----
    {
        const int way = tid >> 6;
        const int px  = tid & 63;
        const float yf = (float)y;
        const float xf = (float)(px0 + px);
        const float2* att = g_att2 + (b << 14);

        float part = 0.f;
        #pragma unroll
        for (int kk = way; kk < KK; kk += 4){
            float4 tc = __ldg(g_tapf + kk);          // (dy-3, dx-3, w0, w1)
            float oy = __half2float(convs[(2*kk  )*CVS + px]);
            float ox = __half2float(convs[(2*kk+1)*CVS + px]);
            float mk = __half2float(convs[(NOFF+kk)*CVS + px]);

            float py  = yf + tc.x + oy;
            float pxx = xf + tc.y + ox;

            float fy = floorf(py), fx = floorf(pxx);
            int y0 = (int)fy, x0 = (int)fx;
            int y1 = y0 + 1,  x1 = x0 + 1;
            float wy1 = py - fy,  wy0 = 1.f - wy1;
            float wx1 = pxx - fx, wx0 = 1.f - wx1;
            float s0 = 0.f, s1 = 0.f;
            bool yv0 = (unsigned)y0 < (unsigned)Hn, yv1 = (unsigned)y1 < (unsigned)Hn;
            bool xv0 = (unsigned)x0 < (unsigned)Wn, xv1 = (unsigned)x1 < (unsigned)Wn;
            if (yv0 && xv0){ float2 v = att[(y0<<7)+x0]; float w = wy0*wx0; s0 += w*v.x; s1 += w*v.y; }
            if (yv0 && xv1){ float2 v = att[(y0<<7)+x1]; float w = wy0*wx1; s0 += w*v.x; s1 += w*v.y; }
            if (yv1 && xv0){ float2 v = att[(y1<<7)+x0]; float w = wy1*wx0; s0 += w*v.x; s1 += w*v.y; }
            if (yv1 && xv1){ float2 v = att[(y1<<7)+x1]; float w = wy1*wx1; s0 += w*v.x; s1 += w*v.y; }

            part += (s0*tc.z + s1*tc.w) * mk;
        }
        parts[way*64 + px] = part;
    }
    __syncthreads();

    if (tid < 64){
        float d = parts[tid] + parts[64+tid] + parts[128+tid] + parts[192+tid];
        g_attmap[(b << 14) + (y << 7) + px0 + tid] = 1.f/(1.f + __expf(-d));
    }
}

// ================= K3: out = x * attmap (streaming) =================
__global__ void dsa_mul_kernel(const float* __restrict__ x,
                               float* __restrict__ out){
    int gid = blockIdx.x * 256 + threadIdx.x;       // float4 index
    float4 xv = __ldcs((const float4*)x + gid);
    int e   = gid << 2;
    int b   = e >> 22;
    int pix = e & 16383;
    float4 a = *(const float4*)(g_attmap + (b << 14) + pix);
    xv.x *= a.x; xv.y *= a.y; xv.z *= a.z; xv.w *= a.w;
    __stcs((float4*)out + gid, xv);
}

// ================= launch =================
extern "C" void kernel_launch(void* const* d_in, const int* in_sizes, int n_in,
                              void* d_out, int out_size){
    const float* x        = (const float*)d_in[0];
    const float* offset_w = (const float*)d_in[1];
    const float* offset_b = (const float*)d_in[2];
    const float* mod_w    = (const float*)d_in[3];
    const float* mod_b    = (const float*)d_in[4];
    const float* dconv_w  = (const float*)d_in[5];
    float* out = (float*)d_out;

    cudaFuncSetAttribute(dsa_fused_kernel,
                         cudaFuncAttributeMaxDynamicSharedMemorySize, SMB_TOTAL);

    dsa_prep_kernel<<<16, 512>>>(offset_w, offset_b, mod_w, mod_b, dconv_w);
    dsa_reduce_kernel<<<256, 128>>>(x);
    dsa_fused_kernel<<<Bn*Hn*2, 256, SMB_TOTAL>>>();
    dsa_mul_kernel<<<(Bn*Cn*HW/4)/256, 256>>>(x, out);
}